// round 7
// baseline (speedup 1.0000x reference)
#include <cuda_runtime.h>

// ---------------------------------------------------------------------------
// KITRO: depth MLP (2 big GEMMs, GEMV fused into GEMM2) + 3-iter refinement.
// B=8192, J=25, FDIM=512, HDIM=1024.  M = B*J = 204800 rows.
//
// GEMM1 computes [features @ [dW1 | cW1[4:,:]]] in one pass:
//   cols 0..1023    -> relu(features@dW1 + db1)      (h1)
//   cols 1024..1055 -> features@cW1[4:] + cb1        (fproj, NO relu)
//   cols 1056..1151 -> zero padding (N padded to 9*128)
// GEMM2 (fused): h2 = relu(h1@dW2+db2) computed per-tile in registers,
//   immediately dotted with dW3 slice; per-row partials atomicAdd'ed into
//   g_depth (zeroed by prep). db3 added later in bones kernel.
// bones: one block per batch element, 3 refinement iterations in smem.
// ---------------------------------------------------------------------------

#define MROWS 204800
#define NB1   1152      // 1024 + 32 + 96 pad  (9 * 128)
#define LDH1  1152
#define K1    512
#define K2    1024
#define N2    512

__device__ float g_Bcat[K1 * NB1];                 //  2.36 MB
__device__ float g_bias1[NB1];
__device__ float g_H1[(size_t)MROWS * LDH1];       // ~944 MB
__device__ float g_depth[MROWS];                   //  0.8 MB

__constant__ int c_par[16] = {0, 0, 0, 0, 0, 0, 5, 7, 6, 8, 5, 6, 11, 13, 12, 14};
__constant__ int c_chi[16] = {1, 2, 3, 4, 5, 6, 7, 9, 8, 10, 11, 12, 13, 15, 14, 16};

// ----------------------------- f32x2 helpers -------------------------------
__device__ __forceinline__ unsigned long long dup_f32(float x) {
    unsigned long long r;
    unsigned int xi = __float_as_uint(x);
    asm("mov.b64 %0, {%1, %1};" : "=l"(r) : "r"(xi));
    return r;
}
__device__ __forceinline__ void fma2(unsigned long long &acc,
                                     unsigned long long a, unsigned long long b) {
    asm("fma.rn.f32x2 %0, %1, %2, %0;" : "+l"(acc) : "l"(a), "l"(b));
}
__device__ __forceinline__ void unpack2(unsigned long long v, float &lo, float &hi) {
    unsigned int l, h;
    asm("mov.b64 {%0, %1}, %2;" : "=r"(l), "=r"(h) : "l"(v));
    lo = __uint_as_float(l);
    hi = __uint_as_float(h);
}

// ------------------------------- prep --------------------------------------
// Build Bcat[512][1152] = [dW1 | cW1[4:516,:] | 0], bias1[1152], zero depth.
__global__ void prep_kernel(const float* __restrict__ dW1, const float* __restrict__ db1,
                            const float* __restrict__ cW1, const float* __restrict__ cb1) {
    int idx = blockIdx.x * blockDim.x + threadIdx.x;
    if (idx < K1 * NB1) {
        int k = idx / NB1;
        int n = idx - k * NB1;
        float v = 0.f;
        if (n < 1024)      v = dW1[k * 1024 + n];
        else if (n < 1056) v = cW1[(4 + k) * 32 + (n - 1024)];
        g_Bcat[idx] = v;
    }
    if (idx < NB1) {
        float v = 0.f;
        if (idx < 1024)      v = db1[idx];
        else if (idx < 1056) v = cb1[idx - 1024];
        g_bias1[idx] = v;
    }
    if (idx < MROWS) g_depth[idx] = 0.f;   // grid covers 589824 >= MROWS
}

// ------------------------------- GEMM --------------------------------------
// Tiles: 128x128x16, 256 threads, 8x8 per-thread microtile, f32x2 packed FMA.
// MODE 0: C = relu_cols<reluN(A@B + bias), stored to C (ldc).
// MODE 1: h = relu(A@B + bias); atomicAdd(depth[row], sum_j h[row,j]*w3[j]).
// Requires M%128==0, N%128==0, K%16==0.
template <int MODE>
__global__ void __launch_bounds__(256, 2)
gemm_ffma2(const float* __restrict__ A, int lda,
           const float* __restrict__ Bm, int ldb,
           const float* __restrict__ bias,
           float* __restrict__ C, int ldc,
           int K, int reluN, const float* __restrict__ w3)
{
    __shared__ __align__(16) float As[16][132];   // A transposed, +4 pad
    __shared__ __align__(16) float Bs[16][128];

    const int tid = threadIdx.x;
    const int bx = blockIdx.x, by = blockIdx.y;
    const int trow = tid >> 4;      // 0..15 -> row group (8 rows)
    const int tcol = tid & 15;      // 0..15 -> col group (8 cols)
    const int lr = tid >> 2;        // 0..63  A-load row
    const int lc = tid & 3;         // 0..3   A-load float4 col
    const int bkk = tid >> 5;       // 0..7   B-load k
    const int bn4 = tid & 31;       // 0..31  B-load float4 col

    const float* Aptr = A + (size_t)(by * 128) * lda;
    const float* Bptr = Bm + bx * 128;

    unsigned long long acc[8][4];
#pragma unroll
    for (int i = 0; i < 8; i++)
#pragma unroll
        for (int j = 0; j < 4; j++) acc[i][j] = 0ULL;

    for (int kt = 0; kt < K; kt += 16) {
        float4 a0 = *(const float4*)(Aptr + (size_t)lr * lda + kt + lc * 4);
        float4 a1 = *(const float4*)(Aptr + (size_t)(lr + 64) * lda + kt + lc * 4);
        float4 b0 = *(const float4*)(Bptr + (size_t)(kt + bkk) * ldb + bn4 * 4);
        float4 b1 = *(const float4*)(Bptr + (size_t)(kt + bkk + 8) * ldb + bn4 * 4);
        __syncthreads();
        As[lc * 4 + 0][lr] = a0.x; As[lc * 4 + 1][lr] = a0.y;
        As[lc * 4 + 2][lr] = a0.z; As[lc * 4 + 3][lr] = a0.w;
        As[lc * 4 + 0][lr + 64] = a1.x; As[lc * 4 + 1][lr + 64] = a1.y;
        As[lc * 4 + 2][lr + 64] = a1.z; As[lc * 4 + 3][lr + 64] = a1.w;
        *(float4*)&Bs[bkk][bn4 * 4] = b0;
        *(float4*)&Bs[bkk + 8][bn4 * 4] = b1;
        __syncthreads();

#pragma unroll
        for (int k = 0; k < 16; k++) {
            float4 av0 = *(const float4*)&As[k][trow * 8];
            float4 av1 = *(const float4*)&As[k][trow * 8 + 4];
            ulonglong2 bv0 = *(const ulonglong2*)&Bs[k][tcol * 8];
            ulonglong2 bv1 = *(const ulonglong2*)&Bs[k][tcol * 8 + 4];
            unsigned long long bb[4] = {bv0.x, bv0.y, bv1.x, bv1.y};
            unsigned long long ad[8];
            ad[0] = dup_f32(av0.x); ad[1] = dup_f32(av0.y);
            ad[2] = dup_f32(av0.z); ad[3] = dup_f32(av0.w);
            ad[4] = dup_f32(av1.x); ad[5] = dup_f32(av1.y);
            ad[6] = dup_f32(av1.z); ad[7] = dup_f32(av1.w);
#pragma unroll
            for (int i = 0; i < 8; i++) {
                fma2(acc[i][0], ad[i], bb[0]);
                fma2(acc[i][1], ad[i], bb[1]);
                fma2(acc[i][2], ad[i], bb[2]);
                fma2(acc[i][3], ad[i], bb[3]);
            }
        }
    }

    const int ncol0 = bx * 128 + tcol * 8;
    float bvals[8];
#pragma unroll
    for (int j = 0; j < 8; j++) bvals[j] = bias[ncol0 + j];

    if (MODE == 0) {
#pragma unroll
        for (int i = 0; i < 8; i++) {
            size_t row = (size_t)(by * 128 + trow * 8 + i);
            float* crow = C + row * ldc + ncol0;
#pragma unroll
            for (int j = 0; j < 4; j++) {
                float v0, v1;
                unpack2(acc[i][j], v0, v1);
                v0 += bvals[j * 2];
                v1 += bvals[j * 2 + 1];
                if (ncol0 + j * 2 < reluN)     v0 = fmaxf(v0, 0.f);
                if (ncol0 + j * 2 + 1 < reluN) v1 = fmaxf(v1, 0.f);
                *(float2*)(crow + j * 2) = make_float2(v0, v1);
            }
        }
    } else {
        // fused relu + dot with dW3 slice + per-row atomic accumulate
        float w3v[8];
#pragma unroll
        for (int j = 0; j < 8; j++) w3v[j] = w3[ncol0 + j];
        float rowsum[8];
#pragma unroll
        for (int i = 0; i < 8; i++) {
            float s = 0.f;
#pragma unroll
            for (int j = 0; j < 4; j++) {
                float v0, v1;
                unpack2(acc[i][j], v0, v1);
                v0 = fmaxf(v0 + bvals[j * 2], 0.f);
                v1 = fmaxf(v1 + bvals[j * 2 + 1], 0.f);
                s += v0 * w3v[j * 2] + v1 * w3v[j * 2 + 1];
            }
            rowsum[i] = s;
        }
        // reduce across the 16 tcol lanes (xor 1,2,4,8 stays in the group)
#pragma unroll
        for (int off = 1; off < 16; off <<= 1)
#pragma unroll
            for (int i = 0; i < 8; i++)
                rowsum[i] += __shfl_xor_sync(0xffffffffu, rowsum[i], off);
        if (tcol == 0) {
            int row0 = by * 128 + trow * 8;
#pragma unroll
            for (int i = 0; i < 8; i++)
                atomicAdd(&g_depth[row0 + i], rowsum[i]);
        }
    }
}

// ------------------------------- bones -------------------------------------
// One block per batch element. 3 refinement iterations, all state in smem.
// base[bone][n] = 0.5*(fproj[parent]+fproj[child])  (cb1 already folded in).
__global__ void __launch_bounds__(256)
bones_kernel(const float* __restrict__ poses2d, const float* __restrict__ conf,
             const float* __restrict__ cW1, const float* __restrict__ cW2,
             const float* __restrict__ cb2, const float* __restrict__ cW3,
             const float* __restrict__ cb3, const float* __restrict__ db3,
             float* __restrict__ out)
{
    __shared__ float p3[75];
    __shared__ float cf[25];
    __shared__ float basef[16][32];
    __shared__ float w1[4][32];
    __shared__ float w2[32][64];
    __shared__ float b2[64];
    __shared__ float w3s[64][3];
    __shared__ float b3[3];
    __shared__ float dir4[16][4];
    __shared__ float g1[16][32];
    __shared__ float g2[16][64];
    __shared__ float bfm[16][3];
    __shared__ float upd[3];

    const int b = blockIdx.x;
    const int tid = threadIdx.x;
    const size_t rowbase = (size_t)b * 25;

    if (tid < 25) cf[tid] = conf[rowbase + tid];
    float db3v = db3[0];
    for (int idx = tid; idx < 75; idx += 256) {
        int j = idx / 3, c = idx - j * 3;
        p3[idx] = (c < 2) ? poses2d[(rowbase + j) * 2 + c]
                          : (g_depth[rowbase + j] + db3v);
    }
    for (int idx = tid; idx < 512; idx += 256) {
        int bone = idx >> 5, n = idx & 31;
        float fp = g_H1[(rowbase + c_par[bone]) * LDH1 + 1024 + n];
        float fc = g_H1[(rowbase + c_chi[bone]) * LDH1 + 1024 + n];
        basef[bone][n] = 0.5f * (fp + fc);
    }
    if (tid < 128) ((float*)w1)[tid] = cW1[tid];          // cW1 rows 0..3
    for (int idx = tid; idx < 2048; idx += 256) ((float*)w2)[idx] = cW2[idx];
    if (tid < 64)  b2[tid] = cb2[tid];
    if (tid < 192) ((float*)w3s)[tid] = cW3[tid];
    if (tid < 3)   b3[tid] = cb3[tid];
    __syncthreads();

    for (int it = 0; it < 3; it++) {
        if (tid < 16) {
            int p = c_par[tid], c = c_chi[tid];
            float vx = p3[c * 3 + 0] - p3[p * 3 + 0];
            float vy = p3[c * 3 + 1] - p3[p * 3 + 1];
            float vz = p3[c * 3 + 2] - p3[p * 3 + 2];
            float len = sqrtf(vx * vx + vy * vy + vz * vz);
            float inv = 1.f / (len + 1e-8f);
            dir4[tid][0] = vx * inv;
            dir4[tid][1] = vy * inv;
            dir4[tid][2] = vz * inv;
            dir4[tid][3] = len;
        }
        __syncthreads();
        for (int idx = tid; idx < 512; idx += 256) {
            int bone = idx >> 5, n = idx & 31;
            float v = basef[bone][n]
                    + dir4[bone][0] * w1[0][n] + dir4[bone][1] * w1[1][n]
                    + dir4[bone][2] * w1[2][n] + dir4[bone][3] * w1[3][n];
            g1[bone][n] = fmaxf(v, 0.f);
        }
        __syncthreads();
        for (int idx = tid; idx < 1024; idx += 256) {
            int bone = idx >> 6, n = idx & 63;
            float s = b2[n];
#pragma unroll
            for (int i = 0; i < 32; i++) s += g1[bone][i] * w2[i][n];
            g2[bone][n] = fmaxf(s, 0.f);
        }
        __syncthreads();
        if (tid < 48) {
            int bone = tid / 3, c = tid - bone * 3;
            float s = b3[c];
#pragma unroll
            for (int i = 0; i < 64; i++) s += g2[bone][i] * w3s[i][c];
            bfm[bone][c] = s;
        }
        __syncthreads();
        if (tid < 3) {
            float s = 0.f;
#pragma unroll
            for (int bone = 0; bone < 16; bone++) s += bfm[bone][tid];
            upd[tid] = 0.1f * (s * (1.f / 16.f));
        }
        __syncthreads();
        for (int idx = tid; idx < 75; idx += 256) {
            int j = idx / 3, c = idx - j * 3;
            p3[idx] = (p3[idx] + upd[c]) * cf[j];
        }
        __syncthreads();
    }

    for (int idx = tid; idx < 75; idx += 256) out[rowbase * 3 + idx] = p3[idx];
}

// ------------------------------ launcher -----------------------------------
extern "C" void kernel_launch(void* const* d_in, const int* in_sizes, int n_in,
                              void* d_out, int out_size) {
    (void)in_sizes; (void)n_in; (void)out_size;
    const float* poses2d  = (const float*)d_in[0];
    const float* features = (const float*)d_in[1];
    const float* conf     = (const float*)d_in[2];
    const float* dW1 = (const float*)d_in[3];
    const float* db1 = (const float*)d_in[4];
    const float* dW2 = (const float*)d_in[5];
    const float* db2 = (const float*)d_in[6];
    const float* dW3 = (const float*)d_in[7];
    const float* db3 = (const float*)d_in[8];
    const float* cW1 = (const float*)d_in[9];
    const float* cb1 = (const float*)d_in[10];
    const float* cW2 = (const float*)d_in[11];
    const float* cb2 = (const float*)d_in[12];
    const float* cW3 = (const float*)d_in[13];
    const float* cb3 = (const float*)d_in[14];
    float* out = (float*)d_out;

    float *pBcat, *pBias1, *pH1;
    cudaGetSymbolAddress((void**)&pBcat, g_Bcat);
    cudaGetSymbolAddress((void**)&pBias1, g_bias1);
    cudaGetSymbolAddress((void**)&pH1, g_H1);

    // 1) build fused [dW1 | cW1'] weight + bias, zero depth accumulator
    prep_kernel<<<(K1 * NB1 + 255) / 256, 256>>>(dW1, db1, cW1, cb1);

    // 2) GEMM1: features[204800,512] @ Bcat[512,1152] -> H1 (relu on cols<1024)
    gemm_ffma2<0><<<dim3(NB1 / 128, MROWS / 128), 256>>>(
        features, K1, pBcat, NB1, pBias1, pH1, LDH1, K1, 1024, nullptr);

    // 3) GEMM2 fused: depth += relu(H1[:, :1024]@dW2+db2) @ dW3
    gemm_ffma2<1><<<dim3(N2 / 128, MROWS / 128), 256>>>(
        pH1, LDH1, dW2, N2, db2, nullptr, 0, K2, N2, dW3);

    // 4) skeletal refinement (adds db3 to depth)
    bones_kernel<<<8192, 256>>>(poses2d, conf, cW1, cW2, cb2, cW3, cb3, db3, out);
}

// round 9
// speedup vs baseline: 4.9559x; 4.9559x over previous
#include <cuda_runtime.h>
#include <cuda_bf16.h>
#include <cstdint>

// ---------------------------------------------------------------------------
// KITRO via warp-level bf16 mma.sync (HMMA.16816) — compute_103-legal.
// B=8192, J=25, FDIM=512, HDIM=1024.  M = B*J = 204800 rows.
//
// GEMM1: H1[204800,1152](bf16) = relu_cols<1024(features @ [dW1|cW1[4:]] + bias)
//        cols 1024..1055 = features@cW1[4:] + cb1 (fproj, no relu)
// GEMM2 (fused GEMV): depth[m] += sum_n relu(H1@dW2+db2)[m,n] * dW3[n]
// bones: one block per batch element, 3 refinement iterations in smem.
// ---------------------------------------------------------------------------

#define MROWS 204800
#define NB1   1152      // 1024 + 32 fproj + 96 pad  (9 * 128)
#define LDH1  1152
#define K1    512
#define K2    1024

#define SPAD  72        // smem row stride in bf16 (64 + 8 pad)

__device__ __nv_bfloat16 g_BT1[NB1 * K1];              // [n][k] transposed weights
__device__ __nv_bfloat16 g_BT2[512 * K2];              // [n][k]
__device__ float         g_bias1[NB1];
__device__ __nv_bfloat16 g_H1[(size_t)MROWS * LDH1];   // ~472 MB
__device__ float         g_depth[MROWS];

__constant__ int c_par[16] = {0, 0, 0, 0, 0, 0, 5, 7, 6, 8, 5, 6, 11, 13, 12, 14};
__constant__ int c_chi[16] = {1, 2, 3, 4, 5, 6, 7, 9, 8, 10, 11, 12, 13, 15, 14, 16};

// ------------------------------ helpers ------------------------------------
__device__ __forceinline__ uint32_t s2u(const void* p) {
    uint32_t a;
    asm("{ .reg .u64 t; cvta.to.shared.u64 t, %1; cvt.u32.u64 %0, t; }"
        : "=r"(a) : "l"(p));
    return a;
}
__device__ __forceinline__ void ldmat_x4(uint32_t* r, uint32_t addr) {
    asm volatile("ldmatrix.sync.aligned.m8n8.x4.shared.b16 {%0,%1,%2,%3}, [%4];"
                 : "=r"(r[0]), "=r"(r[1]), "=r"(r[2]), "=r"(r[3]) : "r"(addr));
}
__device__ __forceinline__ void ldmat_x2(uint32_t* r, uint32_t addr) {
    asm volatile("ldmatrix.sync.aligned.m8n8.x2.shared.b16 {%0,%1}, [%2];"
                 : "=r"(r[0]), "=r"(r[1]) : "r"(addr));
}
__device__ __forceinline__ void mma16816(float* c, const uint32_t* a, const uint32_t* b) {
    asm volatile(
        "mma.sync.aligned.m16n8k16.row.col.f32.bf16.bf16.f32 "
        "{%0,%1,%2,%3}, {%4,%5,%6,%7}, {%8,%9}, {%0,%1,%2,%3};"
        : "+f"(c[0]), "+f"(c[1]), "+f"(c[2]), "+f"(c[3])
        : "r"(a[0]), "r"(a[1]), "r"(a[2]), "r"(a[3]), "r"(b[0]), "r"(b[1]));
}

// ------------------------------- prep --------------------------------------
// BT1[n][k] = [dW1 | cW1[4:] | 0]^T (bf16), BT2[n][k] = dW2^T (bf16),
// bias1 (cb1 folded into cols 1024..1055), zero depth.
__global__ void prep_kernel(const float* __restrict__ dW1, const float* __restrict__ db1,
                            const float* __restrict__ dW2,
                            const float* __restrict__ cW1, const float* __restrict__ cb1) {
    int idx = blockIdx.x * blockDim.x + threadIdx.x;
    if (idx < NB1 * K1) {
        int n = idx / K1, k = idx - n * K1;
        float v = 0.f;
        if (n < 1024)      v = dW1[k * 1024 + n];
        else if (n < 1056) v = cW1[(4 + k) * 32 + (n - 1024)];
        g_BT1[idx] = __float2bfloat16(v);
    } else {
        int j = idx - NB1 * K1;
        if (j < 512 * K2) {
            int n = j / K2, k = j - n * K2;
            g_BT2[j] = __float2bfloat16(dW2[k * 512 + n]);
        }
    }
    if (idx < NB1) {
        float v = 0.f;
        if (idx < 1024)      v = db1[idx];
        else if (idx < 1056) v = cb1[idx - 1024];
        g_bias1[idx] = v;
    }
    if (idx < MROWS) g_depth[idx] = 0.f;
}

// --------------------------- mma.sync GEMM ---------------------------------
// Block tile 128x128, 8 warps (2x4), warp tile 64x32, K chunks of 64.
// ADT: 0 = A is f32 (convert on stage), 1 = A is bf16.
// MODE 0: C(bf16) = relu?(A@B^T + bias)   (relu uniform per 128-col block)
// MODE 1: atomicAdd(g_depth[row], sum_n relu(A@B^T + bias)[n] * w3[n])
template <int ADT, int MODE>
__global__ void __launch_bounds__(256, 2)
gemm_mma(const void* __restrict__ A_, int lda,
         const __nv_bfloat16* __restrict__ BT, int ldb,
         const float* __restrict__ bias,
         __nv_bfloat16* __restrict__ C, int ldc,
         int K, int reluN, const float* __restrict__ w3)
{
    __shared__ __align__(16) __nv_bfloat16 sA[128 * SPAD];   // 18 KB
    __shared__ __align__(16) __nv_bfloat16 sB[128 * SPAD];   // 18 KB
    __shared__ float sAux[128];                               // bias or w3 slice

    const int tid  = threadIdx.x;
    const int wid  = tid >> 5, lane = tid & 31;
    const int wm   = wid >> 2;          // 0..1 -> 64-row slab
    const int wn   = wid & 3;           // 0..3 -> 32-col slab
    const int m0   = blockIdx.y * 128;
    const int n0   = blockIdx.x * 128;

    if (tid < 128)
        sAux[tid] = (MODE == 0) ? bias[n0 + tid]
                                : bias[n0 + tid];   // bias; w3 loaded below
    __shared__ float sW3[128];
    if (MODE == 1 && tid < 128) sW3[tid] = w3[n0 + tid];

    const uint32_t aA = s2u(sA), aB = s2u(sB);

    // ldmatrix base addresses (bytes)
    const uint32_t aAf = aA + (((wm * 64 + (lane & 15)) * SPAD + (lane >> 4) * 8) << 1);
    const uint32_t aBf = aB + (((wn * 32 + (lane & 7)) * SPAD + ((lane >> 3) & 1) * 8) << 1);

    float acc[4][4][4];
#pragma unroll
    for (int i = 0; i < 4; i++)
#pragma unroll
        for (int j = 0; j < 4; j++)
#pragma unroll
            for (int k = 0; k < 4; k++) acc[i][j][k] = 0.f;

    const int nchunks = K >> 6;
    for (int ch = 0; ch < nchunks; ch++) {
        const int k0 = ch << 6;
        __syncthreads();
        // ---- stage A (128 x 64 bf16) ----
        if (ADT == 0) {
#pragma unroll
            for (int i = 0; i < 8; i++) {
                int q = i * 256 + tid;          // 2048 float4-quads
                int row = q >> 4, qc = q & 15;
                const float4 f = *(const float4*)((const float*)A_ +
                                   (size_t)(m0 + row) * lda + k0 + qc * 4);
                __nv_bfloat162 lo = __floats2bfloat162_rn(f.x, f.y);
                __nv_bfloat162 hi = __floats2bfloat162_rn(f.z, f.w);
                uint2 pk = make_uint2(*(uint32_t*)&lo, *(uint32_t*)&hi);
                *(uint2*)&sA[row * SPAD + qc * 4] = pk;
            }
        } else {
#pragma unroll
            for (int i = 0; i < 4; i++) {
                int q = i * 256 + tid;          // 1024 uint4-octs
                int row = q >> 3, oc = q & 7;
                uint4 pk = *(const uint4*)((const __nv_bfloat16*)A_ +
                                           (size_t)(m0 + row) * lda + k0 + oc * 8);
                *(uint4*)&sA[row * SPAD + oc * 8] = pk;
            }
        }
        // ---- stage B^T (128 n-rows x 64 bf16) ----
#pragma unroll
        for (int i = 0; i < 4; i++) {
            int q = i * 256 + tid;
            int row = q >> 3, oc = q & 7;
            uint4 pk = *(const uint4*)(BT + (size_t)(n0 + row) * ldb + k0 + oc * 8);
            *(uint4*)&sB[row * SPAD + oc * 8] = pk;
        }
        __syncthreads();

        // ---- compute: 4 k-steps of 16 ----
#pragma unroll
        for (int ks = 0; ks < 4; ks++) {
            uint32_t af[4][4], bf[4][2];
#pragma unroll
            for (int mt = 0; mt < 4; mt++)
                ldmat_x4(af[mt], aAf + ((mt * 16 * SPAD + ks * 16) << 1));
#pragma unroll
            for (int nt = 0; nt < 4; nt++)
                ldmat_x2(bf[nt], aBf + ((nt * 8 * SPAD + ks * 16) << 1));
#pragma unroll
            for (int mt = 0; mt < 4; mt++)
#pragma unroll
                for (int nt = 0; nt < 4; nt++)
                    mma16816(acc[mt][nt], af[mt], bf[nt]);
        }
    }

    // ------------------------------ epilogue -------------------------------
    const bool dorelu = (n0 < reluN);           // reluN multiple of 128
    const int rbase = m0 + wm * 64 + (lane >> 2);
    const int clocal0 = wn * 32 + (lane & 3) * 2;

    if (MODE == 0) {
#pragma unroll
        for (int mt = 0; mt < 4; mt++) {
            int r0 = rbase + mt * 16;
#pragma unroll
            for (int nt = 0; nt < 4; nt++) {
                int cl = clocal0 + nt * 8;
                float b0 = sAux[cl], b1 = sAux[cl + 1];
                float v0 = acc[mt][nt][0] + b0, v1 = acc[mt][nt][1] + b1;
                float v2 = acc[mt][nt][2] + b0, v3 = acc[mt][nt][3] + b1;
                if (dorelu) {
                    v0 = fmaxf(v0, 0.f); v1 = fmaxf(v1, 0.f);
                    v2 = fmaxf(v2, 0.f); v3 = fmaxf(v3, 0.f);
                }
                *(__nv_bfloat162*)(C + (size_t)r0 * ldc + n0 + cl) =
                    __floats2bfloat162_rn(v0, v1);
                *(__nv_bfloat162*)(C + (size_t)(r0 + 8) * ldc + n0 + cl) =
                    __floats2bfloat162_rn(v2, v3);
            }
        }
    } else {
#pragma unroll
        for (int mt = 0; mt < 4; mt++) {
            float s0 = 0.f, s1 = 0.f;
#pragma unroll
            for (int nt = 0; nt < 4; nt++) {
                int cl = clocal0 + nt * 8;
                float b0 = sAux[cl], b1 = sAux[cl + 1];
                float w0 = sW3[cl],  w1 = sW3[cl + 1];
                s0 += fmaxf(acc[mt][nt][0] + b0, 0.f) * w0
                    + fmaxf(acc[mt][nt][1] + b1, 0.f) * w1;
                s1 += fmaxf(acc[mt][nt][2] + b0, 0.f) * w0
                    + fmaxf(acc[mt][nt][3] + b1, 0.f) * w1;
            }
            s0 += __shfl_xor_sync(0xffffffffu, s0, 1);
            s0 += __shfl_xor_sync(0xffffffffu, s0, 2);
            s1 += __shfl_xor_sync(0xffffffffu, s1, 1);
            s1 += __shfl_xor_sync(0xffffffffu, s1, 2);
            if ((lane & 3) == 0) {
                int r0 = rbase + mt * 16;
                atomicAdd(&g_depth[r0], s0);
                atomicAdd(&g_depth[r0 + 8], s1);
            }
        }
    }
}

// ------------------------------- bones -------------------------------------
__global__ void __launch_bounds__(256)
bones_kernel(const float* __restrict__ poses2d, const float* __restrict__ conf,
             const float* __restrict__ cW1, const float* __restrict__ cW2,
             const float* __restrict__ cb2, const float* __restrict__ cW3,
             const float* __restrict__ cb3, const float* __restrict__ db3,
             float* __restrict__ out)
{
    __shared__ float p3[75];
    __shared__ float cf[25];
    __shared__ float basef[16][32];
    __shared__ float w1[4][32];
    __shared__ float w2[32][64];
    __shared__ float b2[64];
    __shared__ float w3s[64][3];
    __shared__ float b3[3];
    __shared__ float dir4[16][4];
    __shared__ float g1[16][32];
    __shared__ float g2[16][64];
    __shared__ float bfm[16][3];
    __shared__ float upd[3];

    const int b = blockIdx.x;
    const int tid = threadIdx.x;
    const size_t rowbase = (size_t)b * 25;

    if (tid < 25) cf[tid] = conf[rowbase + tid];
    float db3v = db3[0];
    for (int idx = tid; idx < 75; idx += 256) {
        int j = idx / 3, c = idx - j * 3;
        p3[idx] = (c < 2) ? poses2d[(rowbase + j) * 2 + c]
                          : (g_depth[rowbase + j] + db3v);
    }
    for (int idx = tid; idx < 512; idx += 256) {
        int bone = idx >> 5, n = idx & 31;
        float fp = __bfloat162float(g_H1[(rowbase + c_par[bone]) * LDH1 + 1024 + n]);
        float fc = __bfloat162float(g_H1[(rowbase + c_chi[bone]) * LDH1 + 1024 + n]);
        basef[bone][n] = 0.5f * (fp + fc);
    }
    if (tid < 128) ((float*)w1)[tid] = cW1[tid];
    for (int idx = tid; idx < 2048; idx += 256) ((float*)w2)[idx] = cW2[idx];
    if (tid < 64)  b2[tid] = cb2[tid];
    if (tid < 192) ((float*)w3s)[tid] = cW3[tid];
    if (tid < 3)   b3[tid] = cb3[tid];
    __syncthreads();

    for (int it = 0; it < 3; it++) {
        if (tid < 16) {
            int p = c_par[tid], c = c_chi[tid];
            float vx = p3[c * 3 + 0] - p3[p * 3 + 0];
            float vy = p3[c * 3 + 1] - p3[p * 3 + 1];
            float vz = p3[c * 3 + 2] - p3[p * 3 + 2];
            float len = sqrtf(vx * vx + vy * vy + vz * vz);
            float inv = 1.f / (len + 1e-8f);
            dir4[tid][0] = vx * inv;
            dir4[tid][1] = vy * inv;
            dir4[tid][2] = vz * inv;
            dir4[tid][3] = len;
        }
        __syncthreads();
        for (int idx = tid; idx < 512; idx += 256) {
            int bone = idx >> 5, n = idx & 31;
            float v = basef[bone][n]
                    + dir4[bone][0] * w1[0][n] + dir4[bone][1] * w1[1][n]
                    + dir4[bone][2] * w1[2][n] + dir4[bone][3] * w1[3][n];
            g1[bone][n] = fmaxf(v, 0.f);
        }
        __syncthreads();
        for (int idx = tid; idx < 1024; idx += 256) {
            int bone = idx >> 6, n = idx & 63;
            float s = b2[n];
#pragma unroll
            for (int i = 0; i < 32; i++) s += g1[bone][i] * w2[i][n];
            g2[bone][n] = fmaxf(s, 0.f);
        }
        __syncthreads();
        if (tid < 48) {
            int bone = tid / 3, c = tid - bone * 3;
            float s = b3[c];
#pragma unroll
            for (int i = 0; i < 64; i++) s += g2[bone][i] * w3s[i][c];
            bfm[bone][c] = s;
        }
        __syncthreads();
        if (tid < 3) {
            float s = 0.f;
#pragma unroll
            for (int bone = 0; bone < 16; bone++) s += bfm[bone][tid];
            upd[tid] = 0.1f * (s * (1.f / 16.f));
        }
        __syncthreads();
        for (int idx = tid; idx < 75; idx += 256) {
            int j = idx / 3, c = idx - j * 3;
            p3[idx] = (p3[idx] + upd[c]) * cf[j];
        }
        __syncthreads();
    }

    for (int idx = tid; idx < 75; idx += 256) out[rowbase * 3 + idx] = p3[idx];
}

// ------------------------------ launcher -----------------------------------
extern "C" void kernel_launch(void* const* d_in, const int* in_sizes, int n_in,
                              void* d_out, int out_size) {
    (void)in_sizes; (void)n_in; (void)out_size;
    const float* poses2d  = (const float*)d_in[0];
    const float* features = (const float*)d_in[1];
    const float* conf     = (const float*)d_in[2];
    const float* dW1 = (const float*)d_in[3];
    const float* db1 = (const float*)d_in[4];
    const float* dW2 = (const float*)d_in[5];
    const float* db2 = (const float*)d_in[6];
    const float* dW3 = (const float*)d_in[7];
    const float* db3 = (const float*)d_in[8];
    const float* cW1 = (const float*)d_in[9];
    const float* cb1 = (const float*)d_in[10];
    const float* cW2 = (const float*)d_in[11];
    const float* cb2 = (const float*)d_in[12];
    const float* cW3 = (const float*)d_in[13];
    const float* cb3 = (const float*)d_in[14];
    float* out = (float*)d_out;

    __nv_bfloat16 *pBT1, *pBT2, *pH1;
    float *pBias1;
    cudaGetSymbolAddress((void**)&pBT1, g_BT1);
    cudaGetSymbolAddress((void**)&pBT2, g_BT2);
    cudaGetSymbolAddress((void**)&pBias1, g_bias1);
    cudaGetSymbolAddress((void**)&pH1, g_H1);

    // 1) transpose+convert weights, bias fold, zero depth
    int prep_threads = NB1 * K1 + 512 * K2;                // 1,114,112
    prep_kernel<<<(prep_threads + 255) / 256, 256>>>(dW1, db1, dW2, cW1, cb1);

    // 2) GEMM1: H1 = relu_cols<1024(features @ [dW1|cW1'] + bias)  (bf16 out)
    gemm_mma<0, 0><<<dim3(NB1 / 128, MROWS / 128), 256>>>(
        features, K1, pBT1, K1, pBias1, pH1, LDH1, K1, 1024, nullptr);

    // 3) GEMM2 fused GEMV: depth += relu(H1[:, :1024]@dW2+db2) @ dW3
    gemm_mma<1, 1><<<dim3(512 / 128, MROWS / 128), 256>>>(
        pH1, LDH1, pBT2, K2, db2, nullptr, 0, K2, 512, dW3);

    // 4) skeletal refinement (adds db3 to depth)
    bones_kernel<<<8192, 256>>>(poses2d, conf, cW1, cW2, cb2, cW3, cb3, db3, out);
}

// round 10
// speedup vs baseline: 6.0633x; 1.2234x over previous
#include <cuda_runtime.h>
#include <cuda_bf16.h>
#include <cstdint>

// ---------------------------------------------------------------------------
// KITRO via warp-level bf16 mma.sync (HMMA.16816), cp.async double-buffered.
// B=8192, J=25, FDIM=512, HDIM=1024.  M = B*J = 204800 rows.
//
// prep : features -> bf16 (g_Fbf), weights transposed to [n][k] bf16, depth=0
// GEMM1: H1[204800,1024](bf16) = relu(Fbf @ dW1 + db1)
// fproj: g_fproj[204800,32](f32) = Fbf @ cW1[4:] + cb1
// GEMM2 (fused GEMV): depth[m] += sum_n relu(H1@dW2+db2)[m,n] * dW3[n]
// bones: 4 batches per block, 3 refinement iterations in smem.
// ---------------------------------------------------------------------------

#define MROWS 204800
#define K1    512
#define K2    1024
#define SPAD  72                      // smem row stride in bf16 (64 + 8 pad)
#define BUFELEM (128 * SPAD)          // 9216 bf16 per buffer
#define BUFBYTES (BUFELEM * 2)        // 18432
#define GEMM_SMEM (4 * BUFBYTES)      // 73728 bytes dynamic

__device__ __nv_bfloat16 g_Fbf[(size_t)MROWS * K1];    // 210 MB
__device__ __nv_bfloat16 g_BT1[1024 * K1];             // [n][k]
__device__ __nv_bfloat16 g_BTf[32 * K1];               // [n][k] fproj weights
__device__ __nv_bfloat16 g_BT2[512 * K2];              // [n][k]
__device__ __nv_bfloat16 g_H1[(size_t)MROWS * 1024];   // 420 MB
__device__ float         g_fproj[(size_t)MROWS * 32];  // 26 MB
__device__ float         g_depth[MROWS];

__constant__ int c_par[16] = {0, 0, 0, 0, 0, 0, 5, 7, 6, 8, 5, 6, 11, 13, 12, 14};
__constant__ int c_chi[16] = {1, 2, 3, 4, 5, 6, 7, 9, 8, 10, 11, 12, 13, 15, 14, 16};

// ------------------------------ helpers ------------------------------------
__device__ __forceinline__ uint32_t s2u(const void* p) {
    uint32_t a;
    asm("{ .reg .u64 t; cvta.to.shared.u64 t, %1; cvt.u32.u64 %0, t; }"
        : "=r"(a) : "l"(p));
    return a;
}
__device__ __forceinline__ void ldmat_x4(uint32_t* r, uint32_t addr) {
    asm volatile("ldmatrix.sync.aligned.m8n8.x4.shared.b16 {%0,%1,%2,%3}, [%4];"
                 : "=r"(r[0]), "=r"(r[1]), "=r"(r[2]), "=r"(r[3]) : "r"(addr));
}
__device__ __forceinline__ void ldmat_x2(uint32_t* r, uint32_t addr) {
    asm volatile("ldmatrix.sync.aligned.m8n8.x2.shared.b16 {%0,%1}, [%2];"
                 : "=r"(r[0]), "=r"(r[1]) : "r"(addr));
}
__device__ __forceinline__ void mma16816(float* c, const uint32_t* a, const uint32_t* b) {
    asm volatile(
        "mma.sync.aligned.m16n8k16.row.col.f32.bf16.bf16.f32 "
        "{%0,%1,%2,%3}, {%4,%5,%6,%7}, {%8,%9}, {%0,%1,%2,%3};"
        : "+f"(c[0]), "+f"(c[1]), "+f"(c[2]), "+f"(c[3])
        : "r"(a[0]), "r"(a[1]), "r"(a[2]), "r"(a[3]), "r"(b[0]), "r"(b[1]));
}
__device__ __forceinline__ void cpa16(uint32_t dst, const void* src) {
    asm volatile("cp.async.cg.shared.global [%0], [%1], 16;" :: "r"(dst), "l"(src));
}
__device__ __forceinline__ void cp_commit() {
    asm volatile("cp.async.commit_group;" ::: "memory");
}
template <int N> __device__ __forceinline__ void cp_wait() {
    asm volatile("cp.async.wait_group %0;" :: "n"(N) : "memory");
}

// ------------------------------- prep --------------------------------------
__global__ void prep_kernel(const float* __restrict__ features,
                            const float* __restrict__ dW1,
                            const float* __restrict__ dW2,
                            const float* __restrict__ cW1) {
    const int gid = blockIdx.x * blockDim.x + threadIdx.x;
    const int stride = gridDim.x * blockDim.x;
    // features f32 -> bf16, 8 elems per oct
    for (int i = gid; i < MROWS * K1 / 8; i += stride) {
        const float4 f0 = ((const float4*)features)[i * 2];
        const float4 f1 = ((const float4*)features)[i * 2 + 1];
        __nv_bfloat162 p0 = __floats2bfloat162_rn(f0.x, f0.y);
        __nv_bfloat162 p1 = __floats2bfloat162_rn(f0.z, f0.w);
        __nv_bfloat162 p2 = __floats2bfloat162_rn(f1.x, f1.y);
        __nv_bfloat162 p3 = __floats2bfloat162_rn(f1.z, f1.w);
        uint4 pk = make_uint4(*(uint32_t*)&p0, *(uint32_t*)&p1,
                              *(uint32_t*)&p2, *(uint32_t*)&p3);
        ((uint4*)g_Fbf)[i] = pk;
    }
    for (int i = gid; i < 1024 * K1; i += stride) {
        int n = i >> 9, k = i & 511;
        g_BT1[i] = __float2bfloat16(dW1[k * 1024 + n]);
    }
    for (int i = gid; i < 32 * K1; i += stride) {
        int n = i >> 9, k = i & 511;
        g_BTf[i] = __float2bfloat16(cW1[(4 + k) * 32 + n]);
    }
    for (int i = gid; i < 512 * K2; i += stride) {
        int n = i >> 10, k = i & 1023;
        g_BT2[i] = __float2bfloat16(dW2[k * 512 + n]);
    }
    for (int i = gid; i < MROWS; i += stride) g_depth[i] = 0.f;
}

// --------------------- double-buffered mma.sync GEMM -----------------------
// Block tile 128x128, 8 warps (2x4), warp tile 64x32, K chunks of 64.
// MODE 0: C(bf16) = relu(A@B^T + bias)
// MODE 1: atomicAdd(g_depth[row], sum_n relu(A@B^T + bias)[n] * w3[n])
template <int MODE>
__global__ void __launch_bounds__(256, 2)
gemm_db(const __nv_bfloat16* __restrict__ A, int lda,
        const __nv_bfloat16* __restrict__ BT, int ldb,
        const float* __restrict__ bias,
        __nv_bfloat16* __restrict__ C, int ldc,
        int K, const float* __restrict__ w3)
{
    extern __shared__ __align__(16) __nv_bfloat16 smem[];
    __nv_bfloat16* sA = smem;                       // 2 buffers
    __nv_bfloat16* sB = smem + 2 * BUFELEM;         // 2 buffers
    __shared__ float sAux[128];
    __shared__ float sW3[128];

    const int tid  = threadIdx.x;
    const int wid  = tid >> 5, lane = tid & 31;
    const int wm   = wid >> 2;          // 0..1 -> 64-row slab
    const int wn   = wid & 3;           // 0..3 -> 32-col slab
    const int m0   = blockIdx.y * 128;
    const int n0   = blockIdx.x * 128;

    if (tid < 128) sAux[tid] = bias[n0 + tid];
    if (MODE == 1 && tid < 128) sW3[tid] = w3[n0 + tid];

    const uint32_t aA = s2u(sA), aB = s2u(sB);
    const uint32_t aAf = aA + (((wm * 64 + (lane & 15)) * SPAD + (lane >> 4) * 8) << 1);
    const uint32_t aBf = aB + (((wn * 32 + (lane & 7)) * SPAD + ((lane >> 3) & 1) * 8) << 1);

    const int srow = tid >> 3, soc = tid & 7;       // stage: 4 iters x 256 thr

    float acc[4][4][4];
#pragma unroll
    for (int i = 0; i < 4; i++)
#pragma unroll
        for (int j = 0; j < 4; j++)
#pragma unroll
            for (int k = 0; k < 4; k++) acc[i][j][k] = 0.f;

    const int nch = K >> 6;

    // prologue: stage chunk 0 into buffer 0
    {
        const __nv_bfloat16* Ap = A + (size_t)m0 * lda;
        const __nv_bfloat16* Bp = BT + (size_t)n0 * ldb;
#pragma unroll
        for (int i = 0; i < 4; i++) {
            int row = srow + i * 32;
            cpa16(aA + ((row * SPAD + soc * 8) << 1), Ap + (size_t)row * lda + soc * 8);
        }
#pragma unroll
        for (int i = 0; i < 4; i++) {
            int row = srow + i * 32;
            cpa16(aB + ((row * SPAD + soc * 8) << 1), Bp + (size_t)row * ldb + soc * 8);
        }
        cp_commit();
    }

    for (int ch = 0; ch < nch; ch++) {
        if (ch + 1 < nch) {
            const int nb = (ch + 1) & 1;
            const int k0 = (ch + 1) << 6;
            const __nv_bfloat16* Ap = A + (size_t)m0 * lda + k0;
            const __nv_bfloat16* Bp = BT + (size_t)n0 * ldb + k0;
#pragma unroll
            for (int i = 0; i < 4; i++) {
                int row = srow + i * 32;
                cpa16(aA + nb * BUFBYTES + ((row * SPAD + soc * 8) << 1),
                      Ap + (size_t)row * lda + soc * 8);
            }
#pragma unroll
            for (int i = 0; i < 4; i++) {
                int row = srow + i * 32;
                cpa16(aB + nb * BUFBYTES + ((row * SPAD + soc * 8) << 1),
                      Bp + (size_t)row * ldb + soc * 8);
            }
            cp_commit();
            cp_wait<1>();
        } else {
            cp_wait<0>();
        }
        __syncthreads();

        const uint32_t boff = (ch & 1) * BUFBYTES;
#pragma unroll
        for (int ks = 0; ks < 4; ks++) {
            uint32_t af[4][4], bf[4][2];
#pragma unroll
            for (int mt = 0; mt < 4; mt++)
                ldmat_x4(af[mt], aAf + boff + ((mt * 16 * SPAD + ks * 16) << 1));
#pragma unroll
            for (int nt = 0; nt < 4; nt++)
                ldmat_x2(bf[nt], aBf + boff + ((nt * 8 * SPAD + ks * 16) << 1));
#pragma unroll
            for (int mt = 0; mt < 4; mt++)
#pragma unroll
                for (int nt = 0; nt < 4; nt++)
                    mma16816(acc[mt][nt], af[mt], bf[nt]);
        }
        __syncthreads();
    }

    // ------------------------------ epilogue -------------------------------
    const int rbase = m0 + wm * 64 + (lane >> 2);
    const int clocal0 = wn * 32 + (lane & 3) * 2;

    if (MODE == 0) {
#pragma unroll
        for (int mt = 0; mt < 4; mt++) {
            int r0 = rbase + mt * 16;
#pragma unroll
            for (int nt = 0; nt < 4; nt++) {
                int cl = clocal0 + nt * 8;
                float b0 = sAux[cl], b1 = sAux[cl + 1];
                float v0 = fmaxf(acc[mt][nt][0] + b0, 0.f);
                float v1 = fmaxf(acc[mt][nt][1] + b1, 0.f);
                float v2 = fmaxf(acc[mt][nt][2] + b0, 0.f);
                float v3 = fmaxf(acc[mt][nt][3] + b1, 0.f);
                *(__nv_bfloat162*)(C + (size_t)r0 * ldc + n0 + cl) =
                    __floats2bfloat162_rn(v0, v1);
                *(__nv_bfloat162*)(C + (size_t)(r0 + 8) * ldc + n0 + cl) =
                    __floats2bfloat162_rn(v2, v3);
            }
        }
    } else {
#pragma unroll
        for (int mt = 0; mt < 4; mt++) {
            float s0 = 0.f, s1 = 0.f;
#pragma unroll
            for (int nt = 0; nt < 4; nt++) {
                int cl = clocal0 + nt * 8;
                float b0 = sAux[cl], b1 = sAux[cl + 1];
                float w0 = sW3[cl],  w1 = sW3[cl + 1];
                s0 += fmaxf(acc[mt][nt][0] + b0, 0.f) * w0
                    + fmaxf(acc[mt][nt][1] + b1, 0.f) * w1;
                s1 += fmaxf(acc[mt][nt][2] + b0, 0.f) * w0
                    + fmaxf(acc[mt][nt][3] + b1, 0.f) * w1;
            }
            s0 += __shfl_xor_sync(0xffffffffu, s0, 1);
            s0 += __shfl_xor_sync(0xffffffffu, s0, 2);
            s1 += __shfl_xor_sync(0xffffffffu, s1, 1);
            s1 += __shfl_xor_sync(0xffffffffu, s1, 2);
            if ((lane & 3) == 0) {
                int r0 = rbase + mt * 16;
                atomicAdd(&g_depth[r0], s0);
                atomicAdd(&g_depth[r0 + 8], s1);
            }
        }
    }
}

// ------------------------------- fproj -------------------------------------
// g_fproj[204800,32] = Fbf @ BTf^T + cb1.  Block 128 rows, warp tile 16x32.
__global__ void __launch_bounds__(256, 2)
fproj_kernel(const __nv_bfloat16* __restrict__ Fbf,
             const __nv_bfloat16* __restrict__ BTf,
             const float* __restrict__ cb1)
{
    __shared__ __align__(16) __nv_bfloat16 sA[128 * SPAD];   // 18 KB
    __shared__ __align__(16) __nv_bfloat16 sB[32 * SPAD];    // 4.5 KB
    __shared__ float sCb[32];

    const int tid = threadIdx.x;
    const int wid = tid >> 5, lane = tid & 31;
    const int m0 = blockIdx.x * 128;

    if (tid < 32) sCb[tid] = cb1[tid];

    const uint32_t aA = s2u(sA), aB = s2u(sB);
    const uint32_t aAf = aA + (((wid * 16 + (lane & 15)) * SPAD + (lane >> 4) * 8) << 1);
    const uint32_t aBf = aB + (((lane & 7) * SPAD + ((lane >> 3) & 1) * 8) << 1);

    float acc[4][4];
#pragma unroll
    for (int i = 0; i < 4; i++)
#pragma unroll
        for (int j = 0; j < 4; j++) acc[i][j] = 0.f;

    for (int ch = 0; ch < 8; ch++) {
        const int k0 = ch << 6;
        __syncthreads();
#pragma unroll
        for (int i = 0; i < 4; i++) {
            int q = i * 256 + tid, row = q >> 3, oc = q & 7;
            *(uint4*)&sA[row * SPAD + oc * 8] =
                *(const uint4*)(Fbf + (size_t)(m0 + row) * K1 + k0 + oc * 8);
        }
        {
            int row = tid >> 3, oc = tid & 7;   // 256 octs exactly
            *(uint4*)&sB[row * SPAD + oc * 8] =
                *(const uint4*)(BTf + (size_t)row * K1 + k0 + oc * 8);
        }
        __syncthreads();
#pragma unroll
        for (int ks = 0; ks < 4; ks++) {
            uint32_t af[4];
            ldmat_x4(af, aAf + (ks * 16 << 1));
#pragma unroll
            for (int nt = 0; nt < 4; nt++) {
                uint32_t bf[2];
                ldmat_x2(bf, aBf + ((nt * 8 * SPAD + ks * 16) << 1));
                mma16816(acc[nt], af, bf);
            }
        }
    }

    const int r = m0 + wid * 16 + (lane >> 2);
    const int c = (lane & 3) * 2;
#pragma unroll
    for (int nt = 0; nt < 4; nt++) {
        int col = c + nt * 8;
        float b0 = sCb[col], b1 = sCb[col + 1];
        *(float2*)&g_fproj[(size_t)r * 32 + col] =
            make_float2(acc[nt][0] + b0, acc[nt][1] + b1);
        *(float2*)&g_fproj[(size_t)(r + 8) * 32 + col] =
            make_float2(acc[nt][2] + b0, acc[nt][3] + b1);
    }
}

// ------------------------------- bones -------------------------------------
// 4 batches per block (64 threads each), 3 refinement iterations in smem.
__global__ void __launch_bounds__(256)
bones_kernel(const float* __restrict__ poses2d, const float* __restrict__ conf,
             const float* __restrict__ cW1, const float* __restrict__ cW2,
             const float* __restrict__ cb2, const float* __restrict__ cW3,
             const float* __restrict__ cb3, const float* __restrict__ db3,
             float* __restrict__ out)
{
    __shared__ float w1[4][32];
    __shared__ float w2[32][64];
    __shared__ float b2[64];
    __shared__ float w3s[64][3];
    __shared__ float b3[3];
    __shared__ float p3[4][75];
    __shared__ float cf[4][25];
    __shared__ float basef[4][16][32];
    __shared__ float dir4[4][16][4];
    __shared__ float g1[4][16][32];
    __shared__ float g2[4][16][64];
    __shared__ float bfm[4][16][3];
    __shared__ float upd[4][3];

    const int tid = threadIdx.x;
    const int u = tid >> 6, t = tid & 63;
    const size_t rowbase = ((size_t)blockIdx.x * 4 + u) * 25;

    // weights (whole block)
    if (tid < 128) ((float*)w1)[tid] = cW1[tid];
    for (int idx = tid; idx < 2048; idx += 256) ((float*)w2)[idx] = cW2[idx];
    if (tid < 64)  b2[tid] = cb2[tid];
    if (tid < 192) ((float*)w3s)[tid] = cW3[tid];
    if (tid < 3)   b3[tid] = cb3[tid];

    // per-batch state (64 threads each)
    const float db3v = db3[0];
    if (t < 25) cf[u][t] = conf[rowbase + t];
    for (int idx = t; idx < 75; idx += 64) {
        int j = idx / 3, c = idx - j * 3;
        p3[u][idx] = (c < 2) ? poses2d[(rowbase + j) * 2 + c]
                             : (g_depth[rowbase + j] + db3v);
    }
    for (int idx = t; idx < 512; idx += 64) {
        int bone = idx >> 5, n = idx & 31;
        float fp = g_fproj[(rowbase + c_par[bone]) * 32 + n];
        float fc = g_fproj[(rowbase + c_chi[bone]) * 32 + n];
        basef[u][bone][n] = 0.5f * (fp + fc);
    }
    __syncthreads();

    for (int it = 0; it < 3; it++) {
        if (t < 16) {
            int p = c_par[t], c = c_chi[t];
            float vx = p3[u][c * 3 + 0] - p3[u][p * 3 + 0];
            float vy = p3[u][c * 3 + 1] - p3[u][p * 3 + 1];
            float vz = p3[u][c * 3 + 2] - p3[u][p * 3 + 2];
            float len = sqrtf(vx * vx + vy * vy + vz * vz);
            float inv = 1.f / (len + 1e-8f);
            dir4[u][t][0] = vx * inv;
            dir4[u][t][1] = vy * inv;
            dir4[u][t][2] = vz * inv;
            dir4[u][t][3] = len;
        }
        __syncthreads();
        for (int idx = t; idx < 512; idx += 64) {
            int bone = idx >> 5, n = idx & 31;
            float v = basef[u][bone][n]
                    + dir4[u][bone][0] * w1[0][n] + dir4[u][bone][1] * w1[1][n]
                    + dir4[u][bone][2] * w1[2][n] + dir4[u][bone][3] * w1[3][n];
            g1[u][bone][n] = fmaxf(v, 0.f);
        }
        __syncthreads();
        for (int idx = t; idx < 1024; idx += 64) {
            int bone = idx >> 6, n = idx & 63;
            float s = b2[n];
#pragma unroll
            for (int i = 0; i < 32; i++) s += g1[u][bone][i] * w2[i][n];
            g2[u][bone][n] = fmaxf(s, 0.f);
        }
        __syncthreads();
        if (t < 48) {
            int bone = t / 3, c = t - bone * 3;
            float s = b3[c];
#pragma unroll
            for (int i = 0; i < 64; i++) s += g2[u][bone][i] * w3s[i][c];
            bfm[u][bone][c] = s;
        }
        __syncthreads();
        if (t < 3) {
            float s = 0.f;
#pragma unroll
            for (int bone = 0; bone < 16; bone++) s += bfm[u][bone][t];
            upd[u][t] = 0.1f * (s * (1.f / 16.f));
        }
        __syncthreads();
        for (int idx = t; idx < 75; idx += 64) {
            int j = idx / 3, c = idx - j * 3;
            p3[u][idx] = (p3[u][idx] + upd[u][c]) * cf[u][j];
        }
        __syncthreads();
    }

    for (int idx = t; idx < 75; idx += 64) out[rowbase * 3 + idx] = p3[u][idx];
}

// ------------------------------ launcher -----------------------------------
extern "C" void kernel_launch(void* const* d_in, const int* in_sizes, int n_in,
                              void* d_out, int out_size) {
    (void)in_sizes; (void)n_in; (void)out_size;
    const float* poses2d  = (const float*)d_in[0];
    const float* features = (const float*)d_in[1];
    const float* conf     = (const float*)d_in[2];
    const float* dW1 = (const float*)d_in[3];
    const float* db1 = (const float*)d_in[4];
    const float* dW2 = (const float*)d_in[5];
    const float* db2 = (const float*)d_in[6];
    const float* dW3 = (const float*)d_in[7];
    const float* db3 = (const float*)d_in[8];
    const float* cW1 = (const float*)d_in[9];
    const float* cb1 = (const float*)d_in[10];
    const float* cW2 = (const float*)d_in[11];
    const float* cb2 = (const float*)d_in[12];
    const float* cW3 = (const float*)d_in[13];
    const float* cb3 = (const float*)d_in[14];
    float* out = (float*)d_out;

    __nv_bfloat16 *pFbf, *pBT1, *pBTf, *pBT2, *pH1;
    cudaGetSymbolAddress((void**)&pFbf, g_Fbf);
    cudaGetSymbolAddress((void**)&pBT1, g_BT1);
    cudaGetSymbolAddress((void**)&pBTf, g_BTf);
    cudaGetSymbolAddress((void**)&pBT2, g_BT2);
    cudaGetSymbolAddress((void**)&pH1, g_H1);

    cudaFuncSetAttribute(gemm_db<0>, cudaFuncAttributeMaxDynamicSharedMemorySize, GEMM_SMEM);
    cudaFuncSetAttribute(gemm_db<1>, cudaFuncAttributeMaxDynamicSharedMemorySize, GEMM_SMEM);

    // 1) convert features + transpose weights + zero depth
    prep_kernel<<<8192, 256>>>(features, dW1, dW2, cW1);

    // 2) GEMM1: H1 = relu(Fbf @ dW1 + db1)  (bf16 out, N=1024)
    gemm_db<0><<<dim3(8, MROWS / 128), 256, GEMM_SMEM>>>(
        pFbf, K1, pBT1, K1, db1, pH1, 1024, K1, nullptr);

    // 3) fproj: g_fproj = Fbf @ cW1[4:] + cb1  (f32, N=32)
    fproj_kernel<<<MROWS / 128, 256>>>(pFbf, pBTf, cb1);

    // 4) GEMM2 fused GEMV: depth += relu(H1@dW2+db2) @ dW3
    gemm_db<1><<<dim3(4, MROWS / 128), 256, GEMM_SMEM>>>(
        pH1, K2, pBT2, K2, db2, nullptr, 0, K2, dW3);

    // 5) skeletal refinement (adds db3 to depth)
    bones_kernel<<<2048, 256>>>(poses2d, conf, cW1, cW2, cb2, cW3, cb3, db3, out);
}